// round 2
// baseline (speedup 1.0000x reference)
#include <cuda_runtime.h>
#include <math.h>

#define H   128
#define ED  64
#define MAXN 100000
#define MAXE 500000

// ---------------- scratch (device globals; no allocations allowed) ----------------
__device__ float    g_h[(size_t)MAXN * H];      // LN1 output
__device__ float    g_msg[(size_t)MAXE * H];    // gated messages
__device__ float    g_score[MAXE];              // attention scores
__device__ float    g_exp[MAXE];                // exp(score - max)
__device__ unsigned g_maxkey[MAXN];             // ordered-uint segment max
__device__ float    g_denom[MAXN];              // segment sum of exp
__device__ float    g_agg[(size_t)MAXN * H];    // aggregated messages

// ---------------- helpers ----------------
__device__ __forceinline__ float gelu_exact(float v) {
    return 0.5f * v * (1.0f + erff(v * 0.70710678118654752440f));
}

// C[64 edges][128 chans] += A[64][K] * W[K][128]; A in smem (row stride lda),
// W streamed from global through a 32x128 smem tile. 256 threads,
// thread (ti,tj): rows ti*4..+3, cols tj*8..+7.
__device__ __forceinline__ void gemm_acc(
    const float* __restrict__ As, int lda, int aoff,
    const float* __restrict__ Wg, int ldW, int woff,
    int K, float* __restrict__ Wts, float acc[4][8])
{
    int tx = threadIdx.x;
    int ti = tx >> 4, tj = tx & 15;
    int c0 = tj * 8;
    const float* ap[4];
#pragma unroll
    for (int er = 0; er < 4; ++er) ap[er] = As + (ti * 4 + er) * lda + aoff;

    for (int kt = 0; kt < K; kt += 32) {
        __syncthreads();
#pragma unroll
        for (int i = 0; i < 4; ++i) {
            int f4 = tx + i * 256;          // 1024 float4 = 32x128 tile
            int r  = f4 >> 5;
            int c  = (f4 & 31) << 2;
            *(float4*)(Wts + r * 128 + c) =
                *(const float4*)(Wg + (size_t)(kt + r) * ldW + woff + c);
        }
        __syncthreads();
#pragma unroll 16
        for (int kk = 0; kk < 32; ++kk) {
            float av[4];
#pragma unroll
            for (int er = 0; er < 4; ++er) av[er] = ap[er][kt + kk];
            float4 b0 = *(const float4*)(Wts + kk * 128 + c0);
            float4 b1 = *(const float4*)(Wts + kk * 128 + c0 + 4);
            float bv[8] = {b0.x, b0.y, b0.z, b0.w, b1.x, b1.y, b1.z, b1.w};
#pragma unroll
            for (int er = 0; er < 4; ++er)
#pragma unroll
                for (int cj = 0; cj < 8; ++cj)
                    acc[er][cj] = fmaf(av[er], bv[cj], acc[er][cj]);
        }
    }
    __syncthreads();
}

__device__ __forceinline__ void init_acc_bias(float acc[4][8], const float* __restrict__ b) {
    float4 b0 = *(const float4*)b, b1 = *(const float4*)(b + 4);
    float bv[8] = {b0.x, b0.y, b0.z, b0.w, b1.x, b1.y, b1.z, b1.w};
#pragma unroll
    for (int er = 0; er < 4; ++er)
#pragma unroll
        for (int cj = 0; cj < 8; ++cj) acc[er][cj] = bv[cj];
}

__device__ __forceinline__ void store_hidden_gelu(float acc[4][8], float* __restrict__ Hm,
                                                  int e0, int c0) {
#pragma unroll
    for (int er = 0; er < 4; ++er) {
        float* row = Hm + (e0 + er) * 132 + c0;
        float4 v0 = make_float4(gelu_exact(acc[er][0]), gelu_exact(acc[er][1]),
                                gelu_exact(acc[er][2]), gelu_exact(acc[er][3]));
        float4 v1 = make_float4(gelu_exact(acc[er][4]), gelu_exact(acc[er][5]),
                                gelu_exact(acc[er][6]), gelu_exact(acc[er][7]));
        *(float4*)row = v0;
        *(float4*)(row + 4) = v1;
    }
}

// ---------------- K1: LayerNorm1 ----------------
__global__ __launch_bounds__(256) void ln1_kernel(
    const float* __restrict__ x, const float* __restrict__ g,
    const float* __restrict__ b, float* __restrict__ hout, int N)
{
    int node = blockIdx.x * 8 + (threadIdx.x >> 5);
    if (node >= N) return;
    int lane = threadIdx.x & 31;
    float4 v = ((const float4*)(x + (size_t)node * H))[lane];
    float s = v.x + v.y + v.z + v.w;
#pragma unroll
    for (int o = 16; o; o >>= 1) s += __shfl_xor_sync(0xffffffffu, s, o);
    float m = s * (1.0f / 128.0f);
    float dx = v.x - m, dy = v.y - m, dz = v.z - m, dw = v.w - m;
    float ss = dx * dx + dy * dy + dz * dz + dw * dw;
#pragma unroll
    for (int o = 16; o; o >>= 1) ss += __shfl_xor_sync(0xffffffffu, ss, o);
    float r = rsqrtf(ss * (1.0f / 128.0f) + 1e-5f);
    float4 gv = ((const float4*)g)[lane], bv = ((const float4*)b)[lane];
    float4 o4 = make_float4(dx * r * gv.x + bv.x, dy * r * gv.y + bv.y,
                            dz * r * gv.z + bv.z, dw * r * gv.w + bv.w);
    ((float4*)(hout + (size_t)node * H))[lane] = o4;
}

// ---------------- init: zero agg / denom / maxkey ----------------
__global__ __launch_bounds__(256) void init_kernel(int N)
{
    int i = blockIdx.x * 256 + threadIdx.x;
    if (i < N * H) g_agg[i] = 0.0f;
    if (i < N) { g_maxkey[i] = 0u; g_denom[i] = 0.0f; }
}

// ---------------- K2: per-edge MLPs (the big one) ----------------
__global__ __launch_bounds__(256, 1) void edge_kernel(
    const int* __restrict__ esrc, const int* __restrict__ edst,
    const float* __restrict__ emb,
    const float* __restrict__ Wm1, const float* __restrict__ bm1,
    const float* __restrict__ Wm2, const float* __restrict__ bm2,
    const float* __restrict__ Wa1, const float* __restrict__ ba1,
    const float* __restrict__ Wa2, const float* __restrict__ ba2,
    const float* __restrict__ Wg1, const float* __restrict__ bg1,
    const float* __restrict__ Wg2, const float* __restrict__ bg2,
    int E)
{
    extern __shared__ float sm[];
    float* Fe    = sm;                 // [64][324] features [h_dst | h_src | emb]
    float* Hm    = Fe + 64 * 324;      // [64][132] hidden buffer
    float* Wt    = Hm + 64 * 132;      // [32][128] weight tile
    float* gateS = Wt + 32 * 128;      // [64]

    int tx = threadIdx.x;
    int e_base = blockIdx.x * 64;

    { // gather features: 4 threads per edge
        int le = tx >> 2, q = tx & 3;
        int e = e_base + le;
        bool valid = e < E;
        int src = valid ? esrc[e] : 0;
        int dst = valid ? edst[e] : 0;
        const float4* hd = (const float4*)(g_h + (size_t)dst * H);
        const float4* hs = (const float4*)(g_h + (size_t)src * H);
        const float4* em4 = (const float4*)(emb + (size_t)e * ED);
        float4 z = make_float4(0.f, 0.f, 0.f, 0.f);
        float* fr = Fe + le * 324;
#pragma unroll
        for (int jj = 0; jj < 8; ++jj) { int j = q + jj * 4; *(float4*)(fr + j * 4) = valid ? hd[j] : z; }
#pragma unroll
        for (int jj = 0; jj < 8; ++jj) { int j = q + jj * 4; *(float4*)(fr + 128 + j * 4) = valid ? hs[j] : z; }
#pragma unroll
        for (int jj = 0; jj < 4; ++jj) { int j = q + jj * 4; *(float4*)(fr + 256 + j * 4) = valid ? em4[j] : z; }
    }
    __syncthreads();

    int ti = tx >> 4, tj = tx & 15;
    int e0 = ti * 4, c0 = tj * 8;
    float acc[4][8];

    // ---- gate path: gelu(ctx @ Wg1 + bg1) @ Wg2 -> sigmoid
    init_acc_bias(acc, bg1 + c0);
    gemm_acc(Fe, 324, 0, Wg1, 128, 0, 320, Wt, acc);
    store_hidden_gelu(acc, Hm, e0, c0);
    __syncthreads();
    if (tx < 64) {
        float s = 0.f;
        const float* hr = Hm + tx * 132;
        for (int c = 0; c < H; ++c) s += hr[c] * Wg2[c];
        gateS[tx] = 1.0f / (1.0f + expf(-(s + bg2[0])));
    }
    __syncthreads();

    // ---- attn path
    init_acc_bias(acc, ba1 + c0);
    gemm_acc(Fe, 324, 0, Wa1, 128, 0, 320, Wt, acc);
    store_hidden_gelu(acc, Hm, e0, c0);
    __syncthreads();
    if (tx < 64) {
        float s = 0.f;
        const float* hr = Hm + tx * 132;
        for (int c = 0; c < H; ++c) s += hr[c] * Wa2[c];
        int e = e_base + tx;
        if (e < E) g_score[e] = s + ba2[0];
    }
    __syncthreads();

    // ---- msg path: gelu([h_src,emb] @ Wm1 + bm1) @ Wm2 + bm2, then * gate
    init_acc_bias(acc, bm1 + c0);
    gemm_acc(Fe, 324, 128, Wm1, 128, 0, 192, Wt, acc);
    store_hidden_gelu(acc, Hm, e0, c0);
    init_acc_bias(acc, bm2 + c0);
    gemm_acc(Hm, 132, 0, Wm2, 128, 0, 128, Wt, acc);
#pragma unroll
    for (int er = 0; er < 4; ++er) {
        int e = e_base + e0 + er;
        if (e < E) {
            float g = gateS[e0 + er];
            float4 v0 = make_float4(acc[er][0] * g, acc[er][1] * g, acc[er][2] * g, acc[er][3] * g);
            float4 v1 = make_float4(acc[er][4] * g, acc[er][5] * g, acc[er][6] * g, acc[er][7] * g);
            float* mr = g_msg + (size_t)e * H + c0;
            *(float4*)mr = v0;
            *(float4*)(mr + 4) = v1;
        }
    }
}

// ---------------- K3: segment softmax ----------------
__global__ __launch_bounds__(256) void smax_kernel(const int* __restrict__ edst, int E)
{
    int e = blockIdx.x * 256 + threadIdx.x;
    if (e >= E) return;
    int i = __float_as_int(g_score[e]);
    unsigned key = (i >= 0) ? ((unsigned)i ^ 0x80000000u) : ~(unsigned)i;
    atomicMax(&g_maxkey[edst[e]], key);
}

__global__ __launch_bounds__(256) void exps_kernel(const int* __restrict__ edst, int E)
{
    int e = blockIdx.x * 256 + threadIdx.x;
    if (e >= E) return;
    int d = edst[e];
    unsigned k = g_maxkey[d];
    int bits = (k & 0x80000000u) ? (int)(k ^ 0x80000000u) : (int)~k;
    float m = __int_as_float(bits);
    float v = expf(g_score[e] - m);
    g_exp[e] = v;
    atomicAdd(&g_denom[d], v);
}

// ---------------- K4: edge_repr + scatter-add agg ----------------
__global__ __launch_bounds__(256) void scatter_kernel(
    const int* __restrict__ edst, float* __restrict__ erep, int E)
{
    int idx = blockIdx.x * 256 + threadIdx.x;
    int e = idx >> 5;
    if (e >= E) return;
    int l4 = idx & 31;
    int d = edst[e];
    float w = g_exp[e] / fmaxf(g_denom[d], 1e-12f);
    float4 m = ((const float4*)(g_msg + (size_t)e * H))[l4];
    float4 r = make_float4(m.x * w, m.y * w, m.z * w, m.w * w);
    ((float4*)(erep + (size_t)e * H))[l4] = r;
    float* ag = g_agg + (size_t)d * H + (size_t)l4 * 4;
    atomicAdd(ag + 0, r.x);
    atomicAdd(ag + 1, r.y);
    atomicAdd(ag + 2, r.z);
    atomicAdd(ag + 3, r.w);
}

// ---------------- K5: node update + LN2 + FFN ----------------
__global__ __launch_bounds__(256, 1) void node_kernel(
    const float* __restrict__ x,
    const float* __restrict__ Wself, const float* __restrict__ bself,
    const float* __restrict__ Wagg, const float* __restrict__ bagg,
    const float* __restrict__ g2, const float* __restrict__ b2,
    const float* __restrict__ Wf1, const float* __restrict__ bf1,
    const float* __restrict__ Wf2, const float* __restrict__ bf2,
    float* __restrict__ out, int N)
{
    extern __shared__ float sm[];
    float* At   = sm;                  // [64][132] A operand
    float* Ot   = At + 64 * 132;       // [64][132] out1 (pre-LN residual)
    float* H2   = Ot + 64 * 132;       // [64][260] FFN hidden
    float* Wt   = H2 + 64 * 260;       // [32][128]
    float* mu   = Wt + 32 * 128;       // [64]
    float* rstd = mu + 64;             // [64]

    int tx = threadIdx.x;
    int n_base = blockIdx.x * 64;
    int ti = tx >> 4, tj = tx & 15;
    int e0 = ti * 4, c0 = tj * 8;
    float acc[4][8];

    { // gather h
        int le = tx >> 2, q = tx & 3;
        int n = n_base + le;
        bool valid = n < N;
        const float4* hr = (const float4*)(g_h + (size_t)(valid ? n : 0) * H);
        float* ar = At + le * 132;
        float4 z = make_float4(0.f, 0.f, 0.f, 0.f);
#pragma unroll
        for (int jj = 0; jj < 8; ++jj) { int j = q + jj * 4; *(float4*)(ar + j * 4) = valid ? hr[j] : z; }
    }

    { // acc = bself + bagg
        float4 a0 = *(const float4*)(bself + c0), a1 = *(const float4*)(bself + c0 + 4);
        float4 g0 = *(const float4*)(bagg + c0),  g1 = *(const float4*)(bagg + c0 + 4);
        float bv[8] = {a0.x + g0.x, a0.y + g0.y, a0.z + g0.z, a0.w + g0.w,
                       a1.x + g1.x, a1.y + g1.y, a1.z + g1.z, a1.w + g1.w};
#pragma unroll
        for (int er = 0; er < 4; ++er)
#pragma unroll
            for (int cj = 0; cj < 8; ++cj) acc[er][cj] = bv[cj];
    }
    gemm_acc(At, 132, 0, Wself, 128, 0, 128, Wt, acc);

    { // overwrite At with agg (gemm_acc's trailing sync makes this safe)
        int le = tx >> 2, q = tx & 3;
        int n = n_base + le;
        bool valid = n < N;
        const float4* gr = (const float4*)(g_agg + (size_t)(valid ? n : 0) * H);
        float* ar = At + le * 132;
        float4 z = make_float4(0.f, 0.f, 0.f, 0.f);
#pragma unroll
        for (int jj = 0; jj < 8; ++jj) { int j = q + jj * 4; *(float4*)(ar + j * 4) = valid ? gr[j] : z; }
    }
    gemm_acc(At, 132, 0, Wagg, 128, 0, 128, Wt, acc);

    // out1 = x + update -> Ot
#pragma unroll
    for (int er = 0; er < 4; ++er) {
        int n = n_base + e0 + er;
        float4 x0 = make_float4(0.f, 0.f, 0.f, 0.f), x1 = x0;
        if (n < N) {
            x0 = *(const float4*)(x + (size_t)n * H + c0);
            x1 = *(const float4*)(x + (size_t)n * H + c0 + 4);
        }
        float4 o0 = make_float4(acc[er][0] + x0.x, acc[er][1] + x0.y, acc[er][2] + x0.z, acc[er][3] + x0.w);
        float4 o1 = make_float4(acc[er][4] + x1.x, acc[er][5] + x1.y, acc[er][6] + x1.z, acc[er][7] + x1.w);
        float* orow = Ot + (e0 + er) * 132 + c0;
        *(float4*)orow = o0;
        *(float4*)(orow + 4) = o1;
    }
    __syncthreads();

    // LN2 stats (two-pass)
    if (tx < 64) {
        const float* orow = Ot + tx * 132;
        float s = 0.f;
        for (int c = 0; c < H; ++c) s += orow[c];
        float m = s * (1.0f / 128.0f);
        float v = 0.f;
        for (int c = 0; c < H; ++c) { float d = orow[c] - m; v += d * d; }
        mu[tx] = m;
        rstd[tx] = rsqrtf(v * (1.0f / 128.0f) + 1e-5f);
    }
    __syncthreads();

    { // normalize -> At
        int le = tx & 63, cb = tx >> 6;
        float m = mu[le], r = rstd[le];
        const float* orow = Ot + le * 132;
        float* ar = At + le * 132;
#pragma unroll 4
        for (int c = cb * 32; c < cb * 32 + 32; ++c)
            ar[c] = (orow[c] - m) * r * g2[c] + b2[c];
    }

    // FFN layer 1: [64][128] @ [128][256] in two 128-col chunks
    for (int chunk = 0; chunk < 2; ++chunk) {
        int coff = chunk * 128;
        init_acc_bias(acc, bf1 + coff + c0);
        gemm_acc(At, 132, 0, Wf1, 256, coff, 128, Wt, acc);
#pragma unroll
        for (int er = 0; er < 4; ++er) {
            float* hrow = H2 + (e0 + er) * 260 + coff + c0;
            float4 v0 = make_float4(gelu_exact(acc[er][0]), gelu_exact(acc[er][1]),
                                    gelu_exact(acc[er][2]), gelu_exact(acc[er][3]));
            float4 v1 = make_float4(gelu_exact(acc[er][4]), gelu_exact(acc[er][5]),
                                    gelu_exact(acc[er][6]), gelu_exact(acc[er][7]));
            *(float4*)hrow = v0;
            *(float4*)(hrow + 4) = v1;
        }
    }

    // FFN layer 2: [64][256] @ [256][128], + residual -> out
    init_acc_bias(acc, bf2 + c0);
    gemm_acc(H2, 260, 0, Wf2, 128, 0, 256, Wt, acc);
#pragma unroll
    for (int er = 0; er < 4; ++er) {
        int n = n_base + e0 + er;
        if (n < N) {
            const float* orow = Ot + (e0 + er) * 132 + c0;
            float4 o0 = make_float4(orow[0] + acc[er][0], orow[1] + acc[er][1],
                                    orow[2] + acc[er][2], orow[3] + acc[er][3]);
            float4 o1 = make_float4(orow[4] + acc[er][4], orow[5] + acc[er][5],
                                    orow[6] + acc[er][6], orow[7] + acc[er][7]);
            float* po = out + (size_t)n * H + c0;
            *(float4*)po = o0;
            *(float4*)(po + 4) = o1;
        }
    }
}

// ---------------- launch ----------------
extern "C" void kernel_launch(void* const* d_in, const int* in_sizes, int n_in,
                              void* d_out, int out_size)
{
    const float* x     = (const float*)d_in[0];
    const int*   esrc  = (const int*)d_in[1];
    const int*   edst  = (const int*)d_in[2];
    const float* emb   = (const float*)d_in[3];
    const float* ln1g  = (const float*)d_in[4];
    const float* ln1b  = (const float*)d_in[5];
    const float* ln2g  = (const float*)d_in[6];
    const float* ln2b  = (const float*)d_in[7];
    const float* Wself = (const float*)d_in[8];
    const float* bself = (const float*)d_in[9];
    const float* Wm1   = (const float*)d_in[10];
    const float* bm1   = (const float*)d_in[11];
    const float* Wm2   = (const float*)d_in[12];
    const float* bm2   = (const float*)d_in[13];
    const float* Wa1   = (const float*)d_in[14];
    const float* ba1   = (const float*)d_in[15];
    const float* Wa2   = (const float*)d_in[16];
    const float* ba2   = (const float*)d_in[17];
    const float* Wg1   = (const float*)d_in[18];
    const float* bg1   = (const float*)d_in[19];
    const float* Wg2   = (const float*)d_in[20];
    const float* bg2   = (const float*)d_in[21];
    const float* Wagg  = (const float*)d_in[22];
    const float* bagg  = (const float*)d_in[23];
    const float* Wf1   = (const float*)d_in[24];
    const float* bf1   = (const float*)d_in[25];
    const float* Wf2   = (const float*)d_in[26];
    const float* bf2   = (const float*)d_in[27];

    int N = in_sizes[0] / H;
    int E = in_sizes[1];

    float* out_nodes = (float*)d_out;
    float* out_edges = out_nodes + (size_t)N * H;

    const int EDGE_SMEM = (64 * 324 + 64 * 132 + 32 * 128 + 64) * 4;    // 133376
    const int NODE_SMEM = (64 * 132 * 2 + 64 * 260 + 32 * 128 + 128) * 4; // 151040
    cudaFuncSetAttribute(edge_kernel, cudaFuncAttributeMaxDynamicSharedMemorySize, EDGE_SMEM);
    cudaFuncSetAttribute(node_kernel, cudaFuncAttributeMaxDynamicSharedMemorySize, NODE_SMEM);

    float* hbuf;
    cudaGetSymbolAddress((void**)&hbuf, g_h);

    ln1_kernel<<<(N + 7) / 8, 256>>>(x, ln1g, ln1b, hbuf, N);
    init_kernel<<<(N * H + 255) / 256, 256>>>(N);
    edge_kernel<<<(E + 63) / 64, 256, EDGE_SMEM>>>(
        esrc, edst, emb, Wm1, bm1, Wm2, bm2, Wa1, ba1, Wa2, ba2,
        Wg1, bg1, Wg2, bg2, E);
    smax_kernel<<<(E + 255) / 256, 256>>>(edst, E);
    exps_kernel<<<(E + 255) / 256, 256>>>(edst, E);
    scatter_kernel<<<((size_t)E * 32 + 255) / 256, 256>>>(edst, out_edges, E);
    node_kernel<<<(N + 63) / 64, 256, NODE_SMEM>>>(
        x, Wself, bself, Wagg, bagg, ln2g, ln2b, Wf1, bf1, Wf2, bf2,
        out_nodes, N);
}